// round 1
// baseline (speedup 1.0000x reference)
#include <cuda_runtime.h>
#include <cuda_fp16.h>
#include <stdint.h>

#define NN 8192
#define NITER 50

// K = exp(M/eps) in fp16, plus its transpose (both row-major) so BOTH GEMV
// directions use the perfectly-coalesced column-sum pattern.
static __device__ __half g_K [(size_t)NN * NN];
static __device__ __half g_KT[(size_t)NN * NN];
// Per-pass output buffers (atomically accumulated partials); all zeroed at
// launch start so no per-pass zeroing kernels are needed.
static __device__ float g_r[(NITER + 1) * NN];
static __device__ float g_c[(NITER + 1) * NN];
static __device__ float g_trow[NN];
static __device__ float g_tcol[NN];
static __device__ float g_S1[1];

// ---------------------------------------------------------------------------
// init: zero accumulators, set c0 = 1 (psi = 0)
// ---------------------------------------------------------------------------
__global__ void k_init() {
    const int n = (NITER + 1) * NN;
    for (int i = blockIdx.x * blockDim.x + threadIdx.x; i < n;
         i += gridDim.x * blockDim.x) {
        g_r[i] = 0.0f;
        g_c[i] = (i < NN) ? 1.0f : 0.0f;
        if (i < NN) { g_trow[i] = 0.0f; g_tcol[i] = 0.0f; }
        if (i == 0) g_S1[0] = 0.0f;
    }
}

// ---------------------------------------------------------------------------
// build: K = exp(10*M) as fp16, write K and K^T (smem-tiled transpose)
// grid (64,64), 256 threads, 128x128 tile
// ---------------------------------------------------------------------------
__global__ void __launch_bounds__(256) k_build(const float* __restrict__ M) {
    __shared__ __half sm[128][132];   // stride 132 halves -> ~2-way conflicts only
    const int i0 = blockIdx.y << 7;
    const int j0 = blockIdx.x << 7;
    const int tx = threadIdx.x & 31;
    const int ty = threadIdx.x >> 5;

#pragma unroll
    for (int rr = 0; rr < 16; rr++) {
        const int row = ty + (rr << 3);
        const size_t gidx = (size_t)(i0 + row) * NN + j0 + (tx << 2);
        const float4 m4 = *(const float4*)(M + gidx);
        const __half h0 = __float2half_rn(__expf(10.0f * m4.x));
        const __half h1 = __float2half_rn(__expf(10.0f * m4.y));
        const __half h2 = __float2half_rn(__expf(10.0f * m4.z));
        const __half h3 = __float2half_rn(__expf(10.0f * m4.w));
        uint2 pk;
        pk.x = ((uint32_t)__half_as_ushort(h1) << 16) | __half_as_ushort(h0);
        pk.y = ((uint32_t)__half_as_ushort(h3) << 16) | __half_as_ushort(h2);
        *(uint2*)(g_K + gidx) = pk;
        sm[row][(tx << 2) + 0] = h0;
        sm[row][(tx << 2) + 1] = h1;
        sm[row][(tx << 2) + 2] = h2;
        sm[row][(tx << 2) + 3] = h3;
    }
    __syncthreads();
#pragma unroll
    for (int rr = 0; rr < 16; rr++) {
        const int c = ty + (rr << 3);
#pragma unroll
        for (int k = 0; k < 4; k++) {
            const int irow = tx + (k << 5);
            g_KT[(size_t)(j0 + c) * NN + i0 + irow] = sm[irow][c];
        }
    }
}

// ---------------------------------------------------------------------------
// pass: out[c] += sum_r A[r][c] * (2^56 / vin[r]), result rescaled by 2^56.
// Half decoded via exact bit-shift (K > 0 always): f32bits = (h16<<13)&mask,
// value = half * 2^-112. Scale split 2^56/2^56 keeps everything normal fp32.
// grid (8, 64): 1024 cols x 128 rows per block, 128 threads x 8 halves.
// ---------------------------------------------------------------------------
#define TWO56 7.205759403792794e16f

__global__ void __launch_bounds__(128) k_pass(const __half* __restrict__ A,
                                              const float* __restrict__ vin,
                                              float* __restrict__ vout) {
    __shared__ float sw[128];
    const int r0 = blockIdx.y << 7;
    const int c0 = blockIdx.x << 10;
    const int t  = threadIdx.x;
    sw[t] = TWO56 / vin[r0 + t];
    __syncthreads();

    const uint4* __restrict__ p =
        (const uint4*)(A + (size_t)r0 * NN + c0 + (t << 3));

    float a0 = 0.f, a1 = 0.f, a2 = 0.f, a3 = 0.f;
    float a4 = 0.f, a5 = 0.f, a6 = 0.f, a7 = 0.f;

#pragma unroll 8
    for (int r = 0; r < 128; r++) {
        const uint4 q = p[r * (NN / 8)];
        const float w = sw[r];
        a0 = fmaf(__uint_as_float((q.x << 13) & 0x1FFFE000u), w, a0);
        a1 = fmaf(__uint_as_float((q.x >>  3) & 0x1FFFE000u), w, a1);
        a2 = fmaf(__uint_as_float((q.y << 13) & 0x1FFFE000u), w, a2);
        a3 = fmaf(__uint_as_float((q.y >>  3) & 0x1FFFE000u), w, a3);
        a4 = fmaf(__uint_as_float((q.z << 13) & 0x1FFFE000u), w, a4);
        a5 = fmaf(__uint_as_float((q.z >>  3) & 0x1FFFE000u), w, a5);
        a6 = fmaf(__uint_as_float((q.w << 13) & 0x1FFFE000u), w, a6);
        a7 = fmaf(__uint_as_float((q.w >>  3) & 0x1FFFE000u), w, a7);
    }

    float* vo = vout + c0 + (t << 3);
    atomicAdd(vo + 0, a0 * TWO56);
    atomicAdd(vo + 1, a1 * TWO56);
    atomicAdd(vo + 2, a2 * TWO56);
    atomicAdd(vo + 3, a3 * TWO56);
    atomicAdd(vo + 4, a4 * TWO56);
    atomicAdd(vo + 5, a5 * TWO56);
    atomicAdd(vo + 6, a6 * TWO56);
    atomicAdd(vo + 7, a7 * TWO56);
}

// ---------------------------------------------------------------------------
// tredA: S1 = sum(target*M), tcol[j] = sum_i target[i][j]
// grid (16, 64): 512 cols x 128 rows per block, 128 threads x float4
// ---------------------------------------------------------------------------
__global__ void __launch_bounds__(128) k_tredA(const float* __restrict__ tgt,
                                               const float* __restrict__ M) {
    const int r0 = blockIdx.y << 7;
    const int c0 = blockIdx.x << 9;
    const int t  = threadIdx.x;
    const float4* __restrict__ pt =
        (const float4*)(tgt + (size_t)r0 * NN + c0 + (t << 2));
    const float4* __restrict__ pm =
        (const float4*)(M + (size_t)r0 * NN + c0 + (t << 2));

    float cx = 0.f, cy = 0.f, cz = 0.f, cw = 0.f, dot = 0.f;
#pragma unroll 4
    for (int r = 0; r < 128; r++) {
        const float4 tv = pt[r * (NN / 4)];
        const float4 mv = pm[r * (NN / 4)];
        cx += tv.x; cy += tv.y; cz += tv.z; cw += tv.w;
        dot = fmaf(tv.x, mv.x, dot);
        dot = fmaf(tv.y, mv.y, dot);
        dot = fmaf(tv.z, mv.z, dot);
        dot = fmaf(tv.w, mv.w, dot);
    }
    float* tc = g_tcol + c0 + (t << 2);
    atomicAdd(tc + 0, cx);
    atomicAdd(tc + 1, cy);
    atomicAdd(tc + 2, cz);
    atomicAdd(tc + 3, cw);

    __shared__ float sred[128];
    sred[t] = dot;
    __syncthreads();
    for (int s = 64; s > 0; s >>= 1) {
        if (t < s) sred[t] += sred[t + s];
        __syncthreads();
    }
    if (t == 0) atomicAdd(&g_S1[0], sred[0]);
}

// ---------------------------------------------------------------------------
// tredB: trow[i] = sum_j target[i][j] (warp per row, deterministic)
// ---------------------------------------------------------------------------
__global__ void __launch_bounds__(256) k_tredB(const float* __restrict__ tgt) {
    const int w    = threadIdx.x >> 5;
    const int lane = threadIdx.x & 31;
    const int row  = (blockIdx.x << 3) + w;
    const float4* __restrict__ p = (const float4*)(tgt + (size_t)row * NN);
    float s = 0.f;
    for (int j = lane; j < NN / 4; j += 32) {
        const float4 v = p[j];
        s += (v.x + v.y) + (v.z + v.w);
    }
#pragma unroll
    for (int o = 16; o; o >>= 1) s += __shfl_xor_sync(0xFFFFFFFFu, s, o);
    if (lane == 0) g_trow[row] = s;
}

// ---------------------------------------------------------------------------
// final: loss = -S1/eps - loga*sum(trow) + <trow, log r50> + <tcol, log c50>
//   (phi_i = loga - log r_i, psi_j = -log c_j; shift scalars telescope to 0
//    because a,b are uniform and we use plain reciprocal scaling)
// ---------------------------------------------------------------------------
__global__ void __launch_bounds__(1024) k_final(float* __restrict__ out) {
    const int t = threadIdx.x;
    const float* rfin = g_r + (size_t)NITER * NN;
    const float* cfin = g_c + (size_t)NITER * NN;
    float s1 = 0.f, s2 = 0.f, s3 = 0.f;
    for (int i = t; i < NN; i += 1024) {
        const float tr = g_trow[i];
        s1 += tr * logf(rfin[i]);
        s3 += tr;
        s2 += g_tcol[i] * logf(cfin[i]);
    }
    __shared__ float sa[1024], sb[1024], sc[1024];
    sa[t] = s1; sb[t] = s2; sc[t] = s3;
    __syncthreads();
    for (int s = 512; s > 0; s >>= 1) {
        if (t < s) { sa[t] += sa[t + s]; sb[t] += sb[t + s]; sc[t] += sc[t + s]; }
        __syncthreads();
    }
    if (t == 0) {
        const float loga = -9.010913347279288f;  // log(1/8192)
        out[0] = -10.0f * g_S1[0] - loga * sc[0] + sa[0] + sb[0];
    }
}

// ---------------------------------------------------------------------------
extern "C" void kernel_launch(void* const* d_in, const int* in_sizes, int n_in,
                              void* d_out, int out_size) {
    (void)in_sizes; (void)n_in; (void)out_size;
    const float* M   = (const float*)d_in[0];
    const float* tgt = (const float*)d_in[1];
    float* out = (float*)d_out;

    void *pK, *pKT, *pR, *pC;
    cudaGetSymbolAddress(&pK,  g_K);
    cudaGetSymbolAddress(&pKT, g_KT);
    cudaGetSymbolAddress(&pR,  g_r);
    cudaGetSymbolAddress(&pC,  g_c);
    const __half* K  = (const __half*)pK;
    const __half* KT = (const __half*)pKT;
    float* R = (float*)pR;
    float* C = (float*)pC;

    k_init<<<1632, 256>>>();
    k_build<<<dim3(64, 64), 256>>>(M);
    k_tredA<<<dim3(16, 64), 128>>>(tgt, M);
    k_tredB<<<1024, 256>>>(tgt);

    for (int k = 1; k <= NITER; k++) {
        // r_k[i] = sum_j K[i][j] / c_{k-1}[j]  == column-sums of K^T
        k_pass<<<dim3(8, 64), 128>>>(KT, C + (size_t)(k - 1) * NN,
                                     R + (size_t)k * NN);
        // c_k[j] = sum_i K[i][j] / r_k[i]      == column-sums of K
        k_pass<<<dim3(8, 64), 128>>>(K, R + (size_t)k * NN,
                                     C + (size_t)k * NN);
    }
    k_final<<<1, 1024>>>(out);
}

// round 2
// speedup vs baseline: 1.7525x; 1.7525x over previous
#include <cuda_runtime.h>
#include <cuda_fp8.h>
#include <stdint.h>

#define NN 8192
#define NITER 50
#define S1F 9.223372036854776e18f   /* 2^63 */

// K8 = e4m3(exp(10*M) * 2^-6), row-major, 64 MB -> L2-resident hot data.
static __device__ uint32_t g_K8[(size_t)NN * NN / 4];
static __device__ float g_r[(NITER + 1) * NN];
static __device__ float g_c[(NITER + 1) * NN];
static __device__ float g_trow[NN];
static __device__ float g_tcol[NN];
static __device__ float g_S1[1];

// fp8 e4m3 (sign always 0) -> f32 * 2^-120 via exponent-field reuse.
#define DEC(x) __uint_as_float((x) & 0x0FF00000u)

// ---------------------------------------------------------------------------
__global__ void k_init() {
    const int n = (NITER + 1) * NN;
    for (int i = blockIdx.x * blockDim.x + threadIdx.x; i < n;
         i += gridDim.x * blockDim.x) {
        g_r[i] = 0.0f;
        g_c[i] = (i < NN) ? 1.0f : 0.0f;
        if (i < NN) { g_trow[i] = 0.0f; g_tcol[i] = 0.0f; }
        if (i == 0) g_S1[0] = 0.0f;
    }
}

// ---------------------------------------------------------------------------
// build: K8 = e4m3(exp(10*M) * 2^-6). 65536 x 256 covers 16.8M uint32 exactly.
// ---------------------------------------------------------------------------
__global__ void __launch_bounds__(256) k_build(const float* __restrict__ M) {
    const int i = blockIdx.x * 256 + threadIdx.x;
    if (i >= NN * NN / 4) return;
    const float4 m = ((const float4*)M)[i];
    const uint32_t b0 = __nv_cvt_float_to_fp8(__expf(10.0f * m.x) * 0.015625f,
                                              __NV_SATFINITE, __NV_E4M3);
    const uint32_t b1 = __nv_cvt_float_to_fp8(__expf(10.0f * m.y) * 0.015625f,
                                              __NV_SATFINITE, __NV_E4M3);
    const uint32_t b2 = __nv_cvt_float_to_fp8(__expf(10.0f * m.z) * 0.015625f,
                                              __NV_SATFINITE, __NV_E4M3);
    const uint32_t b3 = __nv_cvt_float_to_fp8(__expf(10.0f * m.w) * 0.015625f,
                                              __NV_SATFINITE, __NV_E4M3);
    g_K8[i] = b0 | (b1 << 8) | (b2 << 16) | (b3 << 24);
}

// ---------------------------------------------------------------------------
// passA (row dots): vout[i] += sum_j K[i,j] * (S1F/vin[j]) * S1F
// block = 4 warps x 512 cols = 2048 cols, 128 rows. grid (4, 64).
// Each lane owns 16 fixed cols -> weights live in 16 registers, reused 128x.
// ---------------------------------------------------------------------------
__global__ void __launch_bounds__(128) k_passA(const float* __restrict__ vin,
                                               float* __restrict__ vout) {
    const int w    = threadIdx.x >> 5;
    const int lane = threadIdx.x & 31;
    const int c0   = (blockIdx.x << 11) + (w << 9) + (lane << 4);
    const int r0   = blockIdx.y << 7;

    float wt[16];
#pragma unroll
    for (int k = 0; k < 4; k++) {
        const float4 v = *(const float4*)(vin + c0 + (k << 2));
        wt[k * 4 + 0] = S1F / v.x;
        wt[k * 4 + 1] = S1F / v.y;
        wt[k * 4 + 2] = S1F / v.z;
        wt[k * 4 + 3] = S1F / v.w;
    }

    const uint4* __restrict__ base = reinterpret_cast<const uint4*>(
        reinterpret_cast<const unsigned char*>(g_K8) + (size_t)r0 * NN + c0);

    for (int rg = 0; rg < 128; rg += 8) {
        uint4 q[8];
#pragma unroll
        for (int k = 0; k < 8; k++) q[k] = base[(rg + k) * (NN / 16)];
#pragma unroll
        for (int k = 0; k < 8; k++) {
            float a = 0.0f;
            a = fmaf(DEC(q[k].x << 20), wt[0],  a);
            a = fmaf(DEC(q[k].x << 12), wt[1],  a);
            a = fmaf(DEC(q[k].x <<  4), wt[2],  a);
            a = fmaf(DEC(q[k].x >>  4), wt[3],  a);
            a = fmaf(DEC(q[k].y << 20), wt[4],  a);
            a = fmaf(DEC(q[k].y << 12), wt[5],  a);
            a = fmaf(DEC(q[k].y <<  4), wt[6],  a);
            a = fmaf(DEC(q[k].y >>  4), wt[7],  a);
            a = fmaf(DEC(q[k].z << 20), wt[8],  a);
            a = fmaf(DEC(q[k].z << 12), wt[9],  a);
            a = fmaf(DEC(q[k].z <<  4), wt[10], a);
            a = fmaf(DEC(q[k].z >>  4), wt[11], a);
            a = fmaf(DEC(q[k].w << 20), wt[12], a);
            a = fmaf(DEC(q[k].w << 12), wt[13], a);
            a = fmaf(DEC(q[k].w <<  4), wt[14], a);
            a = fmaf(DEC(q[k].w >>  4), wt[15], a);
#pragma unroll
            for (int o = 16; o; o >>= 1)
                a += __shfl_xor_sync(0xFFFFFFFFu, a, o);
            if (lane == 0) atomicAdd(&vout[r0 + rg + k], a * S1F);
        }
    }
}

// ---------------------------------------------------------------------------
// passB (col sums): vout[j] += sum_i K[i,j] * (S1F/vin[i]) * S1F
// block = 128 threads x 16 cols = 2048 cols, 128 rows. grid (4, 64).
// ---------------------------------------------------------------------------
__global__ void __launch_bounds__(128) k_passB(const float* __restrict__ vin,
                                               float* __restrict__ vout) {
    __shared__ float sw[128];
    const int t  = threadIdx.x;
    const int r0 = blockIdx.y << 7;
    const int c0 = (blockIdx.x << 11) + (t << 4);
    sw[t] = S1F / vin[r0 + t];
    __syncthreads();

    const uint4* __restrict__ base = reinterpret_cast<const uint4*>(
        reinterpret_cast<const unsigned char*>(g_K8) + (size_t)r0 * NN + c0);

    float acc[16];
#pragma unroll
    for (int k = 0; k < 16; k++) acc[k] = 0.0f;

    for (int rg = 0; rg < 128; rg += 8) {
        uint4 q[8];
#pragma unroll
        for (int k = 0; k < 8; k++) q[k] = base[(rg + k) * (NN / 16)];
#pragma unroll
        for (int k = 0; k < 8; k++) {
            const float wv = sw[rg + k];
            acc[0]  = fmaf(DEC(q[k].x << 20), wv, acc[0]);
            acc[1]  = fmaf(DEC(q[k].x << 12), wv, acc[1]);
            acc[2]  = fmaf(DEC(q[k].x <<  4), wv, acc[2]);
            acc[3]  = fmaf(DEC(q[k].x >>  4), wv, acc[3]);
            acc[4]  = fmaf(DEC(q[k].y << 20), wv, acc[4]);
            acc[5]  = fmaf(DEC(q[k].y << 12), wv, acc[5]);
            acc[6]  = fmaf(DEC(q[k].y <<  4), wv, acc[6]);
            acc[7]  = fmaf(DEC(q[k].y >>  4), wv, acc[7]);
            acc[8]  = fmaf(DEC(q[k].z << 20), wv, acc[8]);
            acc[9]  = fmaf(DEC(q[k].z << 12), wv, acc[9]);
            acc[10] = fmaf(DEC(q[k].z <<  4), wv, acc[10]);
            acc[11] = fmaf(DEC(q[k].z >>  4), wv, acc[11]);
            acc[12] = fmaf(DEC(q[k].w << 20), wv, acc[12]);
            acc[13] = fmaf(DEC(q[k].w << 12), wv, acc[13]);
            acc[14] = fmaf(DEC(q[k].w <<  4), wv, acc[14]);
            acc[15] = fmaf(DEC(q[k].w >>  4), wv, acc[15]);
        }
    }
    float* vo = vout + c0;
#pragma unroll
    for (int k = 0; k < 16; k++) atomicAdd(vo + k, acc[k] * S1F);
}

// ---------------------------------------------------------------------------
// fused tred: S1 = sum(t*M), tcol[j] = col-sums(t), trow[i] = row-sums(t).
// Tile 128 rows x 512 cols, 128 threads. grid (16, 64). Single pass over tgt.
// ---------------------------------------------------------------------------
__global__ void __launch_bounds__(128) k_tred(const float* __restrict__ tgt,
                                              const float* __restrict__ M) {
    const int r0 = blockIdx.y << 7;
    const int c0 = blockIdx.x << 9;
    const int t  = threadIdx.x;
    const int lane = t & 31;
    const float4* __restrict__ pt =
        (const float4*)(tgt + (size_t)r0 * NN + c0 + (t << 2));
    const float4* __restrict__ pm =
        (const float4*)(M + (size_t)r0 * NN + c0 + (t << 2));

    float cx = 0.f, cy = 0.f, cz = 0.f, cw = 0.f, dot = 0.f;
    for (int r = 0; r < 128; r++) {
        const float4 tv = pt[r * (NN / 4)];
        const float4 mv = pm[r * (NN / 4)];
        cx += tv.x; cy += tv.y; cz += tv.z; cw += tv.w;
        dot = fmaf(tv.x, mv.x, dot);
        dot = fmaf(tv.y, mv.y, dot);
        dot = fmaf(tv.z, mv.z, dot);
        dot = fmaf(tv.w, mv.w, dot);
        float s4 = (tv.x + tv.y) + (tv.z + tv.w);
#pragma unroll
        for (int o = 16; o; o >>= 1)
            s4 += __shfl_xor_sync(0xFFFFFFFFu, s4, o);
        if (lane == 0) atomicAdd(&g_trow[r0 + r], s4);
    }
    float* tc = g_tcol + c0 + (t << 2);
    atomicAdd(tc + 0, cx);
    atomicAdd(tc + 1, cy);
    atomicAdd(tc + 2, cz);
    atomicAdd(tc + 3, cw);

    __shared__ float sred[128];
    sred[t] = dot;
    __syncthreads();
    for (int s = 64; s > 0; s >>= 1) {
        if (t < s) sred[t] += sred[t + s];
        __syncthreads();
    }
    if (t == 0) atomicAdd(&g_S1[0], sred[0]);
}

// ---------------------------------------------------------------------------
// final: loss = -10*S1 - loga*sum(trow) + <trow, log r50> + <tcol, log c50>
// ---------------------------------------------------------------------------
__global__ void __launch_bounds__(1024) k_final(float* __restrict__ out) {
    const int t = threadIdx.x;
    const float* rfin = g_r + (size_t)NITER * NN;
    const float* cfin = g_c + (size_t)NITER * NN;
    float s1 = 0.f, s2 = 0.f, s3 = 0.f;
    for (int i = t; i < NN; i += 1024) {
        const float tr = g_trow[i];
        s1 += tr * logf(rfin[i]);
        s3 += tr;
        s2 += g_tcol[i] * logf(cfin[i]);
    }
    __shared__ float sa[1024], sb[1024], sc[1024];
    sa[t] = s1; sb[t] = s2; sc[t] = s3;
    __syncthreads();
    for (int s = 512; s > 0; s >>= 1) {
        if (t < s) { sa[t] += sa[t + s]; sb[t] += sb[t + s]; sc[t] += sc[t + s]; }
        __syncthreads();
    }
    if (t == 0) {
        const float loga = -9.010913347279288f;  // log(1/8192)
        out[0] = -10.0f * g_S1[0] - loga * sc[0] + sa[0] + sb[0];
    }
}

// ---------------------------------------------------------------------------
extern "C" void kernel_launch(void* const* d_in, const int* in_sizes, int n_in,
                              void* d_out, int out_size) {
    (void)in_sizes; (void)n_in; (void)out_size;
    const float* M   = (const float*)d_in[0];
    const float* tgt = (const float*)d_in[1];
    float* out = (float*)d_out;

    void *pR, *pC;
    cudaGetSymbolAddress(&pR, g_r);
    cudaGetSymbolAddress(&pC, g_c);
    float* R = (float*)pR;
    float* C = (float*)pC;

    k_init<<<1632, 256>>>();
    k_build<<<NN * NN / 4 / 256, 256>>>(M);
    k_tred<<<dim3(16, 64), 128>>>(tgt, M);

    for (int k = 1; k <= NITER; k++) {
        // r_k[i] = sum_j K[i,j] / c_{k-1}[j]   (row dots)
        k_passA<<<dim3(4, 64), 128>>>(C + (size_t)(k - 1) * NN,
                                      R + (size_t)k * NN);
        // c_k[j] = sum_i K[i,j] / r_k[i]       (col sums)
        k_passB<<<dim3(4, 64), 128>>>(R + (size_t)k * NN,
                                      C + (size_t)k * NN);
    }
    k_final<<<1, 1024>>>(out);
}

// round 3
// speedup vs baseline: 2.3790x; 1.3575x over previous
#include <cuda_runtime.h>
#include <cuda_fp16.h>
#include <cuda_fp8.h>
#include <stdint.h>

#define NN 8192
#define NITER 50
#define CSTAR 0.00390625f     /* 2^-8: weight scale */
/* decoded K = K_true * 2^-14 ; alpha (r scale) = 2^-22, gamma (c scale) = 1 */

static __device__ __align__(256) uint32_t g_K8[(size_t)NN * NN / 4];
static __device__ __align__(16) float g_r[(NITER + 1) * NN];
static __device__ __align__(16) float g_c[(NITER + 1) * NN];
static __device__ float g_trow[NN];
static __device__ float g_tcol[NN];
static __device__ float g_S1[1];

// exact: two e4m3 bytes (sign=0) -> half2 of (value * 2^-8)
static __device__ __forceinline__ __half2 u2h(uint32_t x) {
    return *reinterpret_cast<__half2*>(&x);
}
static __device__ __forceinline__ __half2 dE(uint32_t q) {   // bytes 0,2
    return u2h((q << 7) & 0x7F807F80u);
}
static __device__ __forceinline__ __half2 dO(uint32_t q) {   // bytes 1,3
    return u2h((q >> 1) & 0x7F807F80u);
}

// ---------------------------------------------------------------------------
__global__ void k_init() {
    const int n = (NITER + 1) * NN;
    for (int i = blockIdx.x * blockDim.x + threadIdx.x; i < n;
         i += gridDim.x * blockDim.x) {
        g_r[i] = 0.0f;
        g_c[i] = (i < NN) ? 1.0f : 0.0f;
        if (i < NN) { g_trow[i] = 0.0f; g_tcol[i] = 0.0f; }
        if (i == 0) g_S1[0] = 0.0f;
    }
}

// ---------------------------------------------------------------------------
// build: K8 = e4m3(exp(10*M) * 2^-6)
// ---------------------------------------------------------------------------
__global__ void __launch_bounds__(256) k_build(const float* __restrict__ M) {
    const int i = blockIdx.x * 256 + threadIdx.x;
    if (i >= NN * NN / 4) return;
    const float4 m = ((const float4*)M)[i];
    const uint32_t b0 = __nv_cvt_float_to_fp8(__expf(10.0f * m.x) * 0.015625f,
                                              __NV_SATFINITE, __NV_E4M3);
    const uint32_t b1 = __nv_cvt_float_to_fp8(__expf(10.0f * m.y) * 0.015625f,
                                              __NV_SATFINITE, __NV_E4M3);
    const uint32_t b2 = __nv_cvt_float_to_fp8(__expf(10.0f * m.z) * 0.015625f,
                                              __NV_SATFINITE, __NV_E4M3);
    const uint32_t b3 = __nv_cvt_float_to_fp8(__expf(10.0f * m.w) * 0.015625f,
                                              __NV_SATFINITE, __NV_E4M3);
    g_K8[i] = b0 | (b1 << 8) | (b2 << 16) | (b3 << 24);
}

// ---------------------------------------------------------------------------
// passA (row dots): vout[i] = sum_j Kd[i,j] * (CSTAR / vin[j])
// 512 blocks x 256 thr; block = 16 rows, warp = 2 rows x full 8192 cols.
// Weights prebuilt in smem as pair-shuffled half2: sw[2g]=(w4g,w4g+2),
// sw[2g+1]=(w4g+1,w4g+3) so they align with dE/dO decode order.
// ---------------------------------------------------------------------------
__global__ void __launch_bounds__(256) k_passA(const float* __restrict__ vin,
                                               float* __restrict__ vout) {
    __shared__ __half2 sw[4096];
    const int t = threadIdx.x;
#pragma unroll
    for (int k = 0; k < 8; k++) {
        const int g = t + (k << 8);
        const float4 c4 = *(const float4*)(vin + (g << 2));
        sw[2 * g]     = __floats2half2_rn(__fdividef(CSTAR, c4.x),
                                          __fdividef(CSTAR, c4.z));
        sw[2 * g + 1] = __floats2half2_rn(__fdividef(CSTAR, c4.y),
                                          __fdividef(CSTAR, c4.w));
    }
    __syncthreads();

    const int w = t >> 5, lane = t & 31;
    const int rowa = (blockIdx.x << 4) + (w << 1);
    const uint4* __restrict__ pa =
        ((const uint4*)g_K8) + (size_t)rowa * (NN / 16) + lane;
    const uint4* __restrict__ pb = pa + (NN / 16);
    const uint4* __restrict__ swv = (const uint4*)sw;

    const __half2 z = __floats2half2_rn(0.f, 0.f);
    __half2 aE0 = z, aO0 = z, aE1 = z, aO1 = z;
    __half2 bE0 = z, bO0 = z, bE1 = z, bO1 = z;

#pragma unroll 2
    for (int s = 0; s < 16; s++) {
        const uint4 qa = pa[s * 32];
        const uint4 qb = pb[s * 32];
        const int gi = (s << 6) + (lane << 1);
        const uint4 wv0 = swv[gi];
        const uint4 wv1 = swv[gi + 1];
        aE0 = __hfma2(dE(qa.x), u2h(wv0.x), aE0);
        aO0 = __hfma2(dO(qa.x), u2h(wv0.y), aO0);
        aE1 = __hfma2(dE(qa.y), u2h(wv0.z), aE1);
        aO1 = __hfma2(dO(qa.y), u2h(wv0.w), aO1);
        aE0 = __hfma2(dE(qa.z), u2h(wv1.x), aE0);
        aO0 = __hfma2(dO(qa.z), u2h(wv1.y), aO0);
        aE1 = __hfma2(dE(qa.w), u2h(wv1.z), aE1);
        aO1 = __hfma2(dO(qa.w), u2h(wv1.w), aO1);
        bE0 = __hfma2(dE(qb.x), u2h(wv0.x), bE0);
        bO0 = __hfma2(dO(qb.x), u2h(wv0.y), bO0);
        bE1 = __hfma2(dE(qb.y), u2h(wv0.z), bE1);
        bO1 = __hfma2(dO(qb.y), u2h(wv0.w), bO1);
        bE0 = __hfma2(dE(qb.z), u2h(wv1.x), bE0);
        bO0 = __hfma2(dO(qb.z), u2h(wv1.y), bO0);
        bE1 = __hfma2(dE(qb.w), u2h(wv1.z), bE1);
        bO1 = __hfma2(dO(qb.w), u2h(wv1.w), bO1);
    }

    __half2 sa = __hadd2(__hadd2(aE0, aO0), __hadd2(aE1, aO1));
    __half2 sb = __hadd2(__hadd2(bE0, bO0), __hadd2(bE1, bO1));
    float va = __low2float(sa) + __high2float(sa);
    float vb = __low2float(sb) + __high2float(sb);
#pragma unroll
    for (int o = 16; o; o >>= 1) {
        va += __shfl_xor_sync(0xFFFFFFFFu, va, o);
        vb += __shfl_xor_sync(0xFFFFFFFFu, vb, o);
    }
    if (lane == 0) {
        vout[rowa]     = va;
        vout[rowa + 1] = vb;
    }
}

// ---------------------------------------------------------------------------
// passB (col sums): vout[j] += sum_i Kd[i,j] * (CSTAR / vin[i])
// grid (4,128): block = 64 rows x 2048 cols; thread = 8 cols (uint2/row).
// 4 independent half2 chains, flush to f32 every 32 rows, RED.F32 epilogue.
// ---------------------------------------------------------------------------
__global__ void __launch_bounds__(256) k_passB(const float* __restrict__ vin,
                                               float* __restrict__ vout) {
    __shared__ __half2 swr[64];
    const int t  = threadIdx.x;
    const int r0 = blockIdx.y << 6;
    const int c0 = (blockIdx.x << 11) + (t << 3);
    if (t < 64)
        swr[t] = __float2half2_rn(__fdividef(CSTAR, vin[r0 + t]));
    __syncthreads();

    const uint2* __restrict__ base =
        ((const uint2*)g_K8) + (size_t)r0 * (NN / 8) + (c0 >> 3);

    const __half2 z = __floats2half2_rn(0.f, 0.f);
    __half2 hE0 = z, hO0 = z, hE1 = z, hO1 = z;
    float f0 = 0.f, f1 = 0.f, f2 = 0.f, f3 = 0.f;
    float f4 = 0.f, f5 = 0.f, f6 = 0.f, f7 = 0.f;

#pragma unroll
    for (int half = 0; half < 2; half++) {
#pragma unroll 8
        for (int r = 0; r < 32; r++) {
            const int rr = (half << 5) + r;
            const uint2 q = base[(size_t)rr * (NN / 8)];
            const __half2 wr = swr[rr];
            hE0 = __hfma2(dE(q.x), wr, hE0);
            hO0 = __hfma2(dO(q.x), wr, hO0);
            hE1 = __hfma2(dE(q.y), wr, hE1);
            hO1 = __hfma2(dO(q.y), wr, hO1);
        }
        f0 += __low2float(hE0);  f2 += __high2float(hE0);
        f1 += __low2float(hO0);  f3 += __high2float(hO0);
        f4 += __low2float(hE1);  f6 += __high2float(hE1);
        f5 += __low2float(hO1);  f7 += __high2float(hO1);
        hE0 = z; hO0 = z; hE1 = z; hO1 = z;
    }

    float* vo = vout + c0;
    atomicAdd(vo + 0, f0); atomicAdd(vo + 1, f1);
    atomicAdd(vo + 2, f2); atomicAdd(vo + 3, f3);
    atomicAdd(vo + 4, f4); atomicAdd(vo + 5, f5);
    atomicAdd(vo + 6, f6); atomicAdd(vo + 7, f7);
}

// ---------------------------------------------------------------------------
// fused tred: S1 = sum(t*M), tcol = col-sums(t), trow = row-sums(t)
// ---------------------------------------------------------------------------
__global__ void __launch_bounds__(128) k_tred(const float* __restrict__ tgt,
                                              const float* __restrict__ M) {
    const int r0 = blockIdx.y << 7;
    const int c0 = blockIdx.x << 9;
    const int t  = threadIdx.x;
    const int lane = t & 31;
    const float4* __restrict__ pt =
        (const float4*)(tgt + (size_t)r0 * NN + c0 + (t << 2));
    const float4* __restrict__ pm =
        (const float4*)(M + (size_t)r0 * NN + c0 + (t << 2));

    float cx = 0.f, cy = 0.f, cz = 0.f, cw = 0.f, dot = 0.f;
    for (int r = 0; r < 128; r++) {
        const float4 tv = pt[r * (NN / 4)];
        const float4 mv = pm[r * (NN / 4)];
        cx += tv.x; cy += tv.y; cz += tv.z; cw += tv.w;
        dot = fmaf(tv.x, mv.x, dot);
        dot = fmaf(tv.y, mv.y, dot);
        dot = fmaf(tv.z, mv.z, dot);
        dot = fmaf(tv.w, mv.w, dot);
        float s4 = (tv.x + tv.y) + (tv.z + tv.w);
#pragma unroll
        for (int o = 16; o; o >>= 1)
            s4 += __shfl_xor_sync(0xFFFFFFFFu, s4, o);
        if (lane == 0) atomicAdd(&g_trow[r0 + r], s4);
    }
    float* tc = g_tcol + c0 + (t << 2);
    atomicAdd(tc + 0, cx);
    atomicAdd(tc + 1, cy);
    atomicAdd(tc + 2, cz);
    atomicAdd(tc + 3, cw);

    __shared__ float sred[128];
    sred[t] = dot;
    __syncthreads();
    for (int s = 64; s > 0; s >>= 1) {
        if (t < s) sred[t] += sred[t + s];
        __syncthreads();
    }
    if (t == 0) atomicAdd(&g_S1[0], sred[0]);
}

// ---------------------------------------------------------------------------
// final: loss = -10*S1 + 35*ln2*S3 + <trow, ln R50> + <tcol, ln C50>
//   35*ln2 = 13*ln2 (from -log a = ln 8192) + 22*ln2 (from alpha = 2^-22)
// ---------------------------------------------------------------------------
__global__ void __launch_bounds__(1024) k_final(float* __restrict__ out) {
    const int t = threadIdx.x;
    const float* rfin = g_r + (size_t)NITER * NN;
    const float* cfin = g_c + (size_t)NITER * NN;
    float s1 = 0.f, s2 = 0.f, s3 = 0.f;
    for (int i = t; i < NN; i += 1024) {
        const float tr = g_trow[i];
        s1 += tr * logf(rfin[i]);
        s3 += tr;
        s2 += g_tcol[i] * logf(cfin[i]);
    }
    __shared__ float sa[1024], sb[1024], sc[1024];
    sa[t] = s1; sb[t] = s2; sc[t] = s3;
    __syncthreads();
    for (int s = 512; s > 0; s >>= 1) {
        if (t < s) { sa[t] += sa[t + s]; sb[t] += sb[t + s]; sc[t] += sc[t + s]; }
        __syncthreads();
    }
    if (t == 0) {
        out[0] = -10.0f * g_S1[0] + 24.260151319598086f * sc[0] + sa[0] + sb[0];
    }
}

// ---------------------------------------------------------------------------
extern "C" void kernel_launch(void* const* d_in, const int* in_sizes, int n_in,
                              void* d_out, int out_size) {
    (void)in_sizes; (void)n_in; (void)out_size;
    const float* M   = (const float*)d_in[0];
    const float* tgt = (const float*)d_in[1];
    float* out = (float*)d_out;

    void *pR, *pC;
    cudaGetSymbolAddress(&pR, g_r);
    cudaGetSymbolAddress(&pC, g_c);
    float* R = (float*)pR;
    float* C = (float*)pC;

    k_init<<<1632, 256>>>();
    k_build<<<NN * NN / 4 / 256, 256>>>(M);
    k_tred<<<dim3(16, 64), 128>>>(tgt, M);

    for (int k = 1; k <= NITER; k++) {
        k_passA<<<512, 256>>>(C + (size_t)(k - 1) * NN, R + (size_t)k * NN);
        k_passB<<<dim3(4, 128), 256>>>(R + (size_t)k * NN,
                                       C + (size_t)k * NN);
    }
    k_final<<<1, 1024>>>(out);
}